// round 8
// baseline (speedup 1.0000x reference)
#include <cuda_runtime.h>

// CWT gaus1, scales {1,3,6}, x:(32,4096,64) f32 -> out:(32,3,4096,64) f32.
//
// Folded form: out_a[b,s,c] = sum_m h_a[m] * x[b, s + start_a + m, c]
//   h_a[m] = -sqrt(a)*(f_a[m-1]-f_a[m]),  f_a[i] = int_psi[floor(i/(a*step))]
// Unified window p in [0,61] relative to x[s-31]: scale6 tap m=p (all p),
// scale3 m=p-15 for p in [15,46], scale1 m=p-25 for p in [25,36].
//
// R8: three sequential per-scale passes, each with only an 8-ULL accumulator
// (stored & dead before the next pass) and a 10-ULL ring. Cuts regs 60 -> ~44
// so 5-6 blocks/SM fit (occ 44% -> 62-75%), converting R7's spare issue
// slots into fma-pipe residency. FFMA2 count (the ~26us pipe floor) unchanged.

#define S_LEN 4096
#define C_LEN 64
#define TILE_S 64
#define NROWS 125   // TILE_S + 61
#define NT 256
#define T 8         // seq rows per thread

typedef unsigned long long ull;

// ---------------- compile-time coefficient math ----------------
__host__ __device__ constexpr double cpow2i(int n) {
    double r = 1.0;
    if (n >= 0) { for (int i = 0; i <  n; i++) r *= 2.0; }
    else        { for (int i = 0; i < -n; i++) r *= 0.5; }
    return r;
}
__host__ __device__ constexpr double cexp(double x) {
    const double ln2 = 0.6931471805599453;
    int n = (int)(x / ln2 + (x >= 0.0 ? 0.5 : -0.5));
    double r = x - (double)n * ln2;
    double term = 1.0, sum = 1.0;
    for (int k = 1; k <= 20; k++) { term *= r / (double)k; sum += term; }
    return sum * cpow2i(n);
}
__host__ __device__ constexpr double csqrt_(double x) {
    double g = x > 1.0 ? x : 1.0;
    for (int i = 0; i < 64; i++) g = 0.5 * (g + x / g);
    return g;
}
// Euler-Maclaurin model of numpy cumsum(psi)*step for gaus1 (validated at
// rel_err 4e-7 in R1-R7).
__host__ __device__ constexpr double ipsi_em(long j) {
    const double step = 10.0 / 1023.0;
    double u = (j >= 1023) ? 5.0 : ((double)j * step - 5.0);
    double e = cexp(-u * u);
    double v = e * (1.0 - step * u + (step * step / 12.0) * (4.0 * u * u - 2.0));
    return v / csqrt_(csqrt_(3.141592653589793 / 2.0));   // (pi/2)^(1/4)
}
__host__ __device__ constexpr float f_at(int a, int i, int L) {
    if (i < 0 || i >= L) return 0.0f;
    const double step = 10.0 / 1023.0;
    double as_ = (double)a * step;          // matches numpy a*step (f64)
    long j = (long)((double)i / as_);       // matches arange/(a*step) astype(int64)
    return (float)ipsi_em(j);
}
__host__ __device__ constexpr float hval(int a, int L, int m) {
    float fm1 = f_at(a, m - 1, L), fm = f_at(a, m, L);
    return -(float)csqrt_((double)a) * (fm1 - fm);   // f32 math like reference
}
// exact constexpr float->bits (taps are normal floats, mantissa integer-exact)
__host__ __device__ constexpr unsigned int f2b(float v) {
    if (v == 0.0f) return 0u;
    unsigned int s = 0; double a = (double)v;
    if (a < 0.0) { s = 0x80000000u; a = -a; }
    int e = 0;
    while (a >= 2.0) { a *= 0.5; e++; }
    while (a < 1.0)  { a *= 2.0; e--; }
    unsigned long long m = (unsigned long long)(a * 8388608.0);  // exact
    return s | ((unsigned int)(e + 127) << 23) | ((unsigned int)m & 0x7FFFFFu);
}
__host__ __device__ constexpr ull pk(float v) {
    unsigned int b = f2b(v);
    return ((ull)b << 32) | (ull)b;
}

__device__ __forceinline__ void ffma2(ull &d, ull a, ull b) {
    asm("fma.rn.f32x2 %0, %1, %2, %0;" : "+l"(d) : "l"(a), "l"(b));
}

// ---------------- one pass over taps of a single scale ----------------
// At iter P the ring holds rows P..P+9 (mod 10); uses rows P..P+7,
// prefetches row P+9 (consumed at iter P+2).
template<int P, int P0, int PEND, int A, int L>
__device__ __forceinline__ void pass_step(const float (*xs)[C_LEN], int rbase, int pr,
                                          ull (&win)[10], ull (&Acc)[T]) {
    if constexpr (P < PEND) {
        if constexpr (P + 9 <= PEND + 6)   // rows needed go up to PEND-1+7
            win[(P + 9) % 10] = *(const ull*)&xs[rbase + P + 9][pr * 2];
        constexpr ull c = pk(hval(A, L, P - P0));
        #pragma unroll
        for (int t = 0; t < T; t++)
            ffma2(Acc[t], win[(P + t) % 10], c);
        pass_step<P + 1, P0, PEND, A, L>(xs, rbase, pr, win, Acc);
    }
}

template<int P0, int PEND, int A, int L>
__device__ __forceinline__ void do_pass(const float (*xs)[C_LEN], int rbase, int pr,
                                        ull (&Acc)[T]) {
    ull win[10];
    #pragma unroll
    for (int r = 0; r < 9; r++)
        win[(P0 + r) % 10] = *(const ull*)&xs[rbase + P0 + r][pr * 2];
    pass_step<P0, P0, PEND, A, L>(xs, rbase, pr, win, Acc);
}

// ---------------- kernel ----------------
__global__ void __launch_bounds__(NT)
cwt_kernel(const float* __restrict__ x, float* __restrict__ out) {
    __shared__ float xs[NROWS][C_LEN];

    const int tid = threadIdx.x;
    const int b   = blockIdx.y;
    const int s0  = blockIdx.x * TILE_S;

    // ---- fill smem tile (rows s0-31 .. s0+93, zero-padded at edges) ----
    const float4* xg = (const float4*)x + (size_t)b * (S_LEN * (C_LEN / 4));
    const float4 z4 = make_float4(0.f, 0.f, 0.f, 0.f);
    #pragma unroll
    for (int k = 0; k < 8; k++) {
        int f = tid + k * NT;
        if (f < NROWS * 16) {
            int row = f >> 4, q = f & 15;
            int gs = s0 - 31 + row;
            float4 v = (gs >= 0 && gs < S_LEN) ? xg[gs * 16 + q] : z4;
            *(float4*)&xs[row][q * 4] = v;
        }
    }
    __syncthreads();

    // ---- compute: thread = 2 channels x 8 seq rows, one scale per pass ----
    const int pr    = tid & 31;          // channel pair 0..31
    const int sg    = tid >> 5;          // seq group 0..7
    const int rbase = sg * T;

    ull* og = (ull*)out + (size_t)b * 3 * S_LEN * (C_LEN / 2);
    const int srow = s0 + rbase;
    const size_t plane = (size_t)S_LEN * (C_LEN / 2);

    {   // scale 6: taps p = 0..61
        ull A6[T] = {0,0,0,0,0,0,0,0};
        do_pass<0, 62, 6, 61>(xs, rbase, pr, A6);
        #pragma unroll
        for (int t = 0; t < T; t++)
            og[2 * plane + (size_t)(srow + t) * (C_LEN / 2) + pr] = A6[t];
    }
    {   // scale 3: taps p = 15..46
        ull A3[T] = {0,0,0,0,0,0,0,0};
        do_pass<15, 47, 3, 31>(xs, rbase, pr, A3);
        #pragma unroll
        for (int t = 0; t < T; t++)
            og[1 * plane + (size_t)(srow + t) * (C_LEN / 2) + pr] = A3[t];
    }
    {   // scale 1: taps p = 25..36
        ull A1[T] = {0,0,0,0,0,0,0,0};
        do_pass<25, 37, 1, 11>(xs, rbase, pr, A1);
        #pragma unroll
        for (int t = 0; t < T; t++)
            og[0 * plane + (size_t)(srow + t) * (C_LEN / 2) + pr] = A1[t];
    }
}

extern "C" void kernel_launch(void* const* d_in, const int* in_sizes, int n_in,
                              void* d_out, int out_size) {
    const float* x = (const float*)d_in[0];
    float* out = (float*)d_out;
    dim3 grid(S_LEN / TILE_S, 32);   // (64 seq tiles, 32 batches)
    cwt_kernel<<<grid, NT>>>(x, out);
}